// round 16
// baseline (speedup 1.0000x reference)
#include <cuda_runtime.h>
#include <cstdint>

#define NBATCH 256
#define NTIME  256
#define NS     512
#define NE     128
#define NALPH  128
#define FAN    640
#define BT     (NBATCH * NTIME)

#define NROWT  16
#define NCOLT  8
#define BARPAD 32
#define PITCH  266   // u64/row; 16B-chunk stride 133 ≡ 5 (odd) mod 8 -> conflict-free LDS.128
#define P2     74    // u64/row; chunk stride 37 ≡ 5 (odd) mod 8 -> conflict-free LDS.128

// fragment-pair permutation: k-pair p -> smem slot (pairs p, p+4 adjacent)
#define PERM(p) (((p) & 248) | (((p) & 3) << 1) | (((p) >> 2) & 1))

typedef unsigned long long u64;
typedef unsigned int u32;

// ---- scratch ----
__device__ float g_fin[BT * NS];              // fin[(t*NBATCH+b)*NS + n] fp32
__device__ u64   g_spk_log[BT * 256];         // packed states log (t-major)
__device__ u64   g_state_pk[2][NBATCH * 256]; // HOT packed exchange buffer
__device__ u64   g_emb_pk[NALPH * 64];        // packed emb   [128][64]
__device__ u64   g_wf_pk[NS * 64];            // packed W_f   [512][64]
__device__ u64   g_wout_pk[NALPH * 256];      // packed W_out [128][256]
__device__ int   g_bar[NTIME * NROWT * BARPAD];

// ---- helpers ----
__device__ __forceinline__ float tanh_fast(float x) {
    float y; asm("tanh.approx.f32 %0, %1;" : "=f"(y) : "f"(x)); return y;
}
__device__ __forceinline__ void arrive_release(int* p) {
    asm volatile("red.release.gpu.global.add.u32 [%0], 1;" :: "l"(p) : "memory");
}
__device__ __forceinline__ int ld_acq(const int* p) {
    int v; asm volatile("ld.acquire.gpu.global.b32 %0, [%1];" : "=r"(v) : "l"(p) : "memory");
    return v;
}
__device__ __forceinline__ void stcs_u64(u64* p, u64 v) {
    asm volatile("st.global.cs.b64 [%0], %1;" :: "l"(p), "l"(v) : "memory");
}
__device__ __forceinline__ u64 pack_hl(float v0, float v1) {
    u32 hi, lo;
    asm("cvt.rn.bf16x2.f32 %0, %1, %2;" : "=r"(hi) : "f"(v1), "f"(v0));
    float h0, h1;
    asm("{.reg .b16 x,y;\n\t mov.b32 {x,y}, %2;\n\t cvt.f32.bf16 %0, x;\n\t cvt.f32.bf16 %1, y;}"
        : "=f"(h0), "=f"(h1) : "r"(hi));
    asm("cvt.rn.bf16x2.f32 %0, %1, %2;" : "=r"(lo) : "f"(v1 - h1), "f"(v0 - h0));
    return ((u64)lo << 32) | (u64)hi;
}
__device__ __forceinline__ void mma_bf16(float& d0, float& d1, float& d2, float& d3,
                                         u32 a0, u32 a1, u32 a2, u32 a3,
                                         u32 b0, u32 b1) {
    asm volatile("mma.sync.aligned.m16n8k16.row.col.f32.bf16.bf16.f32 "
                 "{%0,%1,%2,%3}, {%4,%5,%6,%7}, {%8,%9}, {%0,%1,%2,%3};"
                 : "+f"(d0), "+f"(d1), "+f"(d2), "+f"(d3)
                 : "r"(a0), "r"(a1), "r"(a2), "r"(a3), "r"(b0), "r"(b1));
}
__device__ __forceinline__ void mma3(float* d,
                                     u32 ah0, u32 ah1, u32 ah2, u32 ah3,
                                     u32 al0, u32 al1, u32 al2, u32 al3,
                                     u64 bx, u64 by) {
    u32 bh0 = (u32)bx, bh1 = (u32)by;
    u32 bl0 = (u32)(bx >> 32), bl1 = (u32)(by >> 32);
    mma_bf16(d[0], d[1], d[2], d[3], ah0, ah1, ah2, ah3, bh0, bh1);
    mma_bf16(d[0], d[1], d[2], d[3], al0, al1, al2, al3, bh0, bh1);
    mma_bf16(d[0], d[1], d[2], d[3], ah0, ah1, ah2, ah3, bl0, bl1);
}

// =====================================================================
__global__ void reset_kernel() {
    int i = blockIdx.x * blockDim.x + threadIdx.x;
    if (i < NTIME * NROWT) g_bar[i * BARPAD] = 0;
}

__global__ void prep_pack(const float* __restrict__ emb,
                          const float* __restrict__ W_in,
                          const float* __restrict__ W_out) {
    int i = blockIdx.x * blockDim.x + threadIdx.x;
    if (i < NALPH * 64) {
        int r = i >> 6, p = i & 63;
        g_emb_pk[i] = pack_hl(emb[r * NE + 2 * p], emb[r * NE + 2 * p + 1]);
    } else if (i < NALPH * 64 + NS * 64) {
        int j = i - NALPH * 64, n = j >> 6, p = j & 63;
        g_wf_pk[j] = pack_hl(W_in[n * FAN + 2 * p], W_in[n * FAN + 2 * p + 1]);
    } else if (i < NALPH * 64 + NS * 64 + NALPH * 256) {
        int j = i - NALPH * 64 - NS * 64, a = j >> 8, p = j & 255;
        g_wout_pk[j] = pack_hl(W_out[a * NS + 2 * p], W_out[a * NS + 2 * p + 1]);
    }
}

// =====================================================================
// Phase 1: fin via tensor cores.  64(bt) x 64(n) CTA tile, K=128.
// =====================================================================
__global__ void __launch_bounds__(256)
fin_kernel_mma(const int* __restrict__ w,
               const float* __restrict__ b_in) {
    extern __shared__ u64 smf[];
    u64* Aq = smf;             // [64][P2]
    u64* Bq = smf + 64 * P2;   // [64][P2]
    __shared__ int widx[64];

    const int tid  = threadIdx.x;
    const int lane = tid & 31, wrp = tid >> 5;
    const int g    = lane >> 2, tq = lane & 3;
    const int rg   = wrp & 3, ch = wrp >> 2;
    const int bt0  = blockIdx.x * 64;
    const int n0   = blockIdx.y * 64;

    if (tid < 64) {
        int rp = bt0 + tid;
        widx[tid] = w[((rp & 255) << 8) | (rp >> 8)];
    }
    __syncthreads();

    for (int s = tid; s < 64 * 64; s += 256) {
        int row = s >> 6, p = s & 63;
        Aq[row * P2 + PERM(p)] = g_emb_pk[widx[row] * 64 + p];
    }
    for (int s = tid; s < 64 * 64; s += 256) {
        int row = s >> 6, p = s & 63;
        Bq[row * P2 + PERM(p)] = g_wf_pk[(n0 + row) * 64 + p];
    }
    __syncthreads();

    const u64* ar0 = Aq + (rg * 16 + g) * P2;
    const u64* ar1 = ar0 + 8 * P2;
    const u64* br0 = Bq + (ch * 32 + g) * P2;
    const u64* br1 = br0 + 8 * P2;
    const u64* br2 = br0 + 16 * P2;
    const u64* br3 = br0 + 24 * P2;

    float d[4][4] = {};
    #pragma unroll
    for (int kk = 0; kk < 8; ++kk) {
        int off = 8 * kk + 2 * tq;
        ulonglong2 A0 = *(const ulonglong2*)(ar0 + off);
        ulonglong2 A1 = *(const ulonglong2*)(ar1 + off);
        u32 ah0=(u32)A0.x, ah1=(u32)A1.x, ah2=(u32)A0.y, ah3=(u32)A1.y;
        u32 al0=(u32)(A0.x>>32), al1=(u32)(A1.x>>32);
        u32 al2=(u32)(A0.y>>32), al3=(u32)(A1.y>>32);
        ulonglong2 B0 = *(const ulonglong2*)(br0 + off);
        ulonglong2 B1 = *(const ulonglong2*)(br1 + off);
        ulonglong2 B2 = *(const ulonglong2*)(br2 + off);
        ulonglong2 B3 = *(const ulonglong2*)(br3 + off);
        mma3(d[0], ah0,ah1,ah2,ah3, al0,al1,al2,al3, B0.x, B0.y);
        mma3(d[1], ah0,ah1,ah2,ah3, al0,al1,al2,al3, B1.x, B1.y);
        mma3(d[2], ah0,ah1,ah2,ah3, al0,al1,al2,al3, B2.x, B2.y);
        mma3(d[3], ah0,ah1,ah2,ah3, al0,al1,al2,al3, B3.x, B3.y);
    }

    int row0 = bt0 + rg * 16 + g, row1 = row0 + 8;
    #pragma unroll
    for (int j = 0; j < 4; ++j) {
        int col = n0 + ch * 32 + 8 * j + 2 * tq;
        float2 bi = *(const float2*)&b_in[col];
        *(float2*)&g_fin[row0 * NS + col] = make_float2(d[j][0] + bi.x, d[j][1] + bi.y);
        *(float2*)&g_fin[row1 * NS + col] = make_float2(d[j][2] + bi.x, d[j][3] + bi.y);
    }
}

// =====================================================================
// Phase 2: persistent recurrent kernel (R15 structure, fixed pitch).
// =====================================================================
__global__ void __launch_bounds__(256, 1)
rnn_kernel(const float* __restrict__ W_in) {
    extern __shared__ u64 smq[];
    u64*   Bq  = smq;                          // [64][PITCH]
    u64*   Aq  = smq + 64 * PITCH;             // [16][PITCH]
    float* Red = (float*)(smq + 80 * PITCH);   // [4][32][8]

    const int tid  = threadIdx.x;
    const int wrp  = tid >> 5;
    const int lane = tid & 31;
    const int g    = lane >> 2;
    const int tq   = lane & 3;
    const int cg   = wrp & 3;
    const int kh   = wrp >> 2;
    const int rowtile = blockIdx.x >> 3;
    const int coltile = blockIdx.x & 7;
    const int rb0 = rowtile * 16;
    const int cb0 = coltile * 64;

    for (int s = tid; s < 64 * 256; s += 256) {
        int n = s >> 8, p = s & 255;
        const float* wp = &W_in[(cb0 + n) * FAN + NE + 2 * p];
        Bq[n * PITCH + PERM(p)] = pack_hl(wp[0], wp[1]);
    }
    __syncthreads();

    const u64* arow0 = Aq + g * PITCH;
    const u64* arow1 = Aq + (g + 8) * PITCH;
    const u64* brow0 = Bq + (16 * cg + g) * PITCH;
    const u64* brow1 = Bq + (16 * cg + g + 8) * PITCH;

    const int r0 = rb0 + g, r1 = rb0 + g + 8;
    const int c0 = cb0 + 16 * cg + 2 * tq;
    const int c1 = c0 + 8;
    const int pg0 = c0 >> 1, pg1 = pg0 + 4;
    const int kbase = kh * 16;

    const int srow = tid >> 4;
    const int sp0  = tid & 15;

    float* redp = &Red[(cg * 32 + lane) * 8];

    float2 f00, f01, f10, f11;
    if (kh == 0) {
        f00 = *(const float2*)&g_fin[r0 * NS + c0];
        f01 = *(const float2*)&g_fin[r0 * NS + c1];
        f10 = *(const float2*)&g_fin[r1 * NS + c0];
        f11 = *(const float2*)&g_fin[r1 * NS + c1];
    }

    for (int t = 0; t < NTIME; ++t) {
        float d0=0.f,d1=0.f,d2=0.f,d3=0.f,d4=0.f,d5=0.f,d6=0.f,d7=0.f;

        if (t > 0) {
            const int* bar = &g_bar[((t - 1) * NROWT + rowtile) * BARPAD];
            while (ld_acq(bar) < NCOLT) { }

            const u64* src = &g_state_pk[(t - 1) & 1][(rb0 + srow) << 8];
            u64* dst = &Aq[srow * PITCH];
            #pragma unroll
            for (int j = 0; j < 16; ++j) {
                int idx = sp0 + 16 * j;
                dst[PERM(idx)] = __ldcg(&src[idx]);
            }
            __syncthreads();

            #pragma unroll
            for (int cc = 0; cc < 16; ++cc) {
                int off = 8 * (kbase + cc) + 2 * tq;
                ulonglong2 A0 = *(const ulonglong2*)(arow0 + off);
                ulonglong2 A1 = *(const ulonglong2*)(arow1 + off);
                ulonglong2 B0 = *(const ulonglong2*)(brow0 + off);
                ulonglong2 B1 = *(const ulonglong2*)(brow1 + off);
                u32 ah0 = (u32)A0.x, ah1 = (u32)A1.x, ah2 = (u32)A0.y, ah3 = (u32)A1.y;
                u32 al0 = (u32)(A0.x >> 32), al1 = (u32)(A1.x >> 32);
                u32 al2 = (u32)(A0.y >> 32), al3 = (u32)(A1.y >> 32);
                u32 bh0 = (u32)B0.x, bh1 = (u32)B0.y;
                u32 bl0 = (u32)(B0.x >> 32), bl1 = (u32)(B0.y >> 32);
                u32 ch0 = (u32)B1.x, ch1 = (u32)B1.y;
                u32 cl0 = (u32)(B1.x >> 32), cl1 = (u32)(B1.y >> 32);
                mma_bf16(d0,d1,d2,d3, ah0,ah1,ah2,ah3, bh0,bh1);
                mma_bf16(d0,d1,d2,d3, al0,al1,al2,al3, bh0,bh1);
                mma_bf16(d0,d1,d2,d3, ah0,ah1,ah2,ah3, bl0,bl1);
                mma_bf16(d4,d5,d6,d7, ah0,ah1,ah2,ah3, ch0,ch1);
                mma_bf16(d4,d5,d6,d7, al0,al1,al2,al3, ch0,ch1);
                mma_bf16(d4,d5,d6,d7, ah0,ah1,ah2,ah3, cl0,cl1);
            }

            if (kh == 1) {
                redp[0]=d0; redp[1]=d1; redp[2]=d2; redp[3]=d3;
                redp[4]=d4; redp[5]=d5; redp[6]=d6; redp[7]=d7;
            }
            __syncthreads();
            if (kh == 0) {
                d0 += redp[0]; d1 += redp[1]; d2 += redp[2]; d3 += redp[3];
                d4 += redp[4]; d5 += redp[5]; d6 += redp[6]; d7 += redp[7];
            }
        }

        if (kh == 0) {
            float v0 = tanh_fast(d0 + f00.x), v1 = tanh_fast(d1 + f00.y);
            float v2 = tanh_fast(d2 + f10.x), v3 = tanh_fast(d3 + f10.y);
            float v4 = tanh_fast(d4 + f01.x), v5 = tanh_fast(d5 + f01.y);
            float v6 = tanh_fast(d6 + f11.x), v7 = tanh_fast(d7 + f11.y);

            u64 pk00 = pack_hl(v0, v1), pk10 = pack_hl(v2, v3);
            u64 pk01 = pack_hl(v4, v5), pk11 = pack_hl(v6, v7);

            const int sel = t & 1;
            g_state_pk[sel][(r0 << 8) + pg0] = pk00;
            g_state_pk[sel][(r1 << 8) + pg0] = pk10;
            g_state_pk[sel][(r0 << 8) + pg1] = pk01;
            g_state_pk[sel][(r1 << 8) + pg1] = pk11;

            stcs_u64(&g_spk_log[(((unsigned)t * NBATCH + r0) << 8) + pg0], pk00);
            stcs_u64(&g_spk_log[(((unsigned)t * NBATCH + r1) << 8) + pg0], pk10);
            stcs_u64(&g_spk_log[(((unsigned)t * NBATCH + r0) << 8) + pg1], pk01);
            stcs_u64(&g_spk_log[(((unsigned)t * NBATCH + r1) << 8) + pg1], pk11);
        }
        __syncthreads();

        if (t + 1 < NTIME) {
            if (tid == 0)
                arrive_release(&g_bar[(t * NROWT + rowtile) * BARPAD]);
            if (kh == 0) {
                f00 = __ldcg((const float2*)&g_fin[((t + 1) * NBATCH + r0) * NS + c0]);
                f01 = __ldcg((const float2*)&g_fin[((t + 1) * NBATCH + r0) * NS + c1]);
                f10 = __ldcg((const float2*)&g_fin[((t + 1) * NBATCH + r1) * NS + c0]);
                f11 = __ldcg((const float2*)&g_fin[((t + 1) * NBATCH + r1) * NS + c1]);
            }
        }
    }
}

// =====================================================================
// Phase 3: y via tensor cores.  64(bt) x 64(a) CTA tile, K=512 (4 chunks).
// =====================================================================
__global__ void __launch_bounds__(256)
out_kernel_mma(const float* __restrict__ b_out,
               float* __restrict__ y) {
    extern __shared__ u64 smo[];
    u64* Aq = smo;             // [64][P2]
    u64* Bq = smo + 64 * P2;   // [64][P2]
    __shared__ int rowmap[64];

    const int tid  = threadIdx.x;
    const int lane = tid & 31, wrp = tid >> 5;
    const int g    = lane >> 2, tq = lane & 3;
    const int rg   = wrp & 3, ch = wrp >> 2;
    const int bt0  = blockIdx.x * 64;
    const int a0   = blockIdx.y * 64;

    if (tid < 64) {
        int r = bt0 + tid;
        rowmap[tid] = ((r & 255) << 8) | (r >> 8);
    }
    __syncthreads();

    const u64* ar0 = Aq + (rg * 16 + g) * P2;
    const u64* ar1 = ar0 + 8 * P2;
    const u64* br0 = Bq + (ch * 32 + g) * P2;
    const u64* br1 = br0 + 8 * P2;
    const u64* br2 = br0 + 16 * P2;
    const u64* br3 = br0 + 24 * P2;

    float d[4][4] = {};

    for (int kc = 0; kc < 4; ++kc) {
        for (int s = tid; s < 64 * 64; s += 256) {
            int row = s >> 6, p = s & 63;
            Aq[row * P2 + PERM(p)] =
                __ldcg(&g_spk_log[rowmap[row] * 256 + 64 * kc + p]);
        }
        for (int s = tid; s < 64 * 64; s += 256) {
            int row = s >> 6, p = s & 63;
            Bq[row * P2 + PERM(p)] = g_wout_pk[(a0 + row) * 256 + 64 * kc + p];
        }
        __syncthreads();

        #pragma unroll
        for (int kk = 0; kk < 8; ++kk) {
            int off = 8 * kk + 2 * tq;
            ulonglong2 A0 = *(const ulonglong2*)(ar0 + off);
            ulonglong2 A1 = *(const ulonglong2*)(ar1 + off);
            u32 ah0=(u32)A0.x, ah1=(u32)A1.x, ah2=(u32)A0.y, ah3=(u32)A1.y;
            u32 al0=(u32)(A0.x>>32), al1=(u32)(A1.x>>32);
            u32 al2=(u32)(A0.y>>32), al3=(u32)(A1.y>>32);
            ulonglong2 B0 = *(const ulonglong2*)(br0 + off);
            ulonglong2 B1 = *(const ulonglong2*)(br1 + off);
            ulonglong2 B2 = *(const ulonglong2*)(br2 + off);
            ulonglong2 B3 = *(const ulonglong2*)(br3 + off);
            mma3(d[0], ah0,ah1,ah2,ah3, al0,al1,al2,al3, B0.x, B0.y);
            mma3(d[1], ah0,ah1,ah2,ah3, al0,al1,al2,al3, B1.x, B1.y);
            mma3(d[2], ah0,ah1,ah2,ah3, al0,al1,al2,al3, B2.x, B2.y);
            mma3(d[3], ah0,ah1,ah2,ah3, al0,al1,al2,al3, B3.x, B3.y);
        }
        __syncthreads();
    }

    int row0 = bt0 + rg * 16 + g, row1 = row0 + 8;
    #pragma unroll
    for (int j = 0; j < 4; ++j) {
        int col = a0 + ch * 32 + 8 * j + 2 * tq;
        float2 bo = *(const float2*)&b_out[col];
        *(float2*)&y[row0 * NALPH + col] = make_float2(d[j][0] + bo.x, d[j][1] + bo.y);
        *(float2*)&y[row1 * NALPH + col] = make_float2(d[j][2] + bo.x, d[j][3] + bo.y);
    }
}

// =====================================================================
// launch: reset, prep, fin, rnn, out   (rnn = 4th launch -> profiled)
// =====================================================================
extern "C" void kernel_launch(void* const* d_in, const int* in_sizes, int n_in,
                              void* d_out, int out_size) {
    const int*   w     = (const int*)  d_in[0];
    const float* emb   = (const float*)d_in[1];
    const float* W_in  = (const float*)d_in[2];
    const float* b_in  = (const float*)d_in[3];
    const float* W_out = (const float*)d_in[4];
    const float* b_out = (const float*)d_in[5];
    float* y = (float*)d_out;

    size_t rnn_smem = (size_t)80 * PITCH * sizeof(u64) + 4 * 32 * 8 * sizeof(float);
    size_t gem_smem = (size_t)128 * P2 * sizeof(u64);
    cudaFuncSetAttribute(rnn_kernel,
                         cudaFuncAttributeMaxDynamicSharedMemorySize, (int)rnn_smem);
    cudaFuncSetAttribute(fin_kernel_mma,
                         cudaFuncAttributeMaxDynamicSharedMemorySize, (int)gem_smem);
    cudaFuncSetAttribute(out_kernel_mma,
                         cudaFuncAttributeMaxDynamicSharedMemorySize, (int)gem_smem);

    reset_kernel<<<(NTIME * NROWT + 255) / 256, 256>>>();
    prep_pack<<<(NALPH * 64 + NS * 64 + NALPH * 256 + 255) / 256, 256>>>(emb, W_in, W_out);
    fin_kernel_mma<<<dim3(BT / 64, NS / 64), 256, gem_smem>>>(w, b_in);
    rnn_kernel<<<128, 256, rnn_smem>>>(W_in);
    out_kernel_mma<<<dim3(BT / 64, NALPH / 64), 256, gem_smem>>>(b_out, y);
}

// round 17
// speedup vs baseline: 1.4194x; 1.4194x over previous
#include <cuda_runtime.h>
#include <cstdint>

#define NBATCH 256
#define NTIME  256
#define NS     512
#define NE     128
#define NALPH  128
#define FAN    640
#define BT     (NBATCH * NTIME)

#define NROWT  16
#define NCOLT  8
#define BARPAD 32
#define PITCH  264   // u64/row; chunk stride 132 ≡ 4 mod 8 -> conflict-free (verified R14/R16)
#define P2     72    // u64/row; chunk stride 36  ≡ 4 mod 8 -> conflict-free

// fragment-pair permutation: k-pair p -> smem slot (pairs p, p+4 adjacent)
#define PERM(p) (((p) & 248) | (((p) & 3) << 1) | (((p) >> 2) & 1))

typedef unsigned long long u64;
typedef unsigned int u32;

// ---- scratch ----
__device__ float g_fin[BT * NS];              // fin[(t*NBATCH+b)*NS + n] fp32
__device__ u64   g_spk_log[BT * 256];         // packed states log (t-major)
__device__ u64   g_state_pk[2][NBATCH * 256]; // HOT packed exchange buffer
__device__ u64   g_emb_pk[NALPH * 64];        // packed emb   [128][64]
__device__ u64   g_wf_pk[NS * 64];            // packed W_f   [512][64]
__device__ u64   g_wout_pk[NALPH * 256];      // packed W_out [128][256]
__device__ int   g_bar[NTIME * NROWT * BARPAD];

// ---- helpers ----
__device__ __forceinline__ float tanh_fast(float x) {
    float y; asm("tanh.approx.f32 %0, %1;" : "=f"(y) : "f"(x)); return y;
}
__device__ __forceinline__ void arrive_release(int* p) {
    asm volatile("red.release.gpu.global.add.u32 [%0], 1;" :: "l"(p) : "memory");
}
__device__ __forceinline__ int ld_acq(const int* p) {
    int v; asm volatile("ld.acquire.gpu.global.b32 %0, [%1];" : "=r"(v) : "l"(p) : "memory");
    return v;
}
__device__ __forceinline__ void stcs_u64(u64* p, u64 v) {
    asm volatile("st.global.cs.b64 [%0], %1;" :: "l"(p), "l"(v) : "memory");
}
__device__ __forceinline__ u64 pack_hl(float v0, float v1) {
    u32 hi, lo;
    asm("cvt.rn.bf16x2.f32 %0, %1, %2;" : "=r"(hi) : "f"(v1), "f"(v0));
    float h0, h1;
    asm("{.reg .b16 x,y;\n\t mov.b32 {x,y}, %2;\n\t cvt.f32.bf16 %0, x;\n\t cvt.f32.bf16 %1, y;}"
        : "=f"(h0), "=f"(h1) : "r"(hi));
    asm("cvt.rn.bf16x2.f32 %0, %1, %2;" : "=r"(lo) : "f"(v1 - h1), "f"(v0 - h0));
    return ((u64)lo << 32) | (u64)hi;
}
__device__ __forceinline__ void mma_bf16(float& d0, float& d1, float& d2, float& d3,
                                         u32 a0, u32 a1, u32 a2, u32 a3,
                                         u32 b0, u32 b1) {
    asm volatile("mma.sync.aligned.m16n8k16.row.col.f32.bf16.bf16.f32 "
                 "{%0,%1,%2,%3}, {%4,%5,%6,%7}, {%8,%9}, {%0,%1,%2,%3};"
                 : "+f"(d0), "+f"(d1), "+f"(d2), "+f"(d3)
                 : "r"(a0), "r"(a1), "r"(a2), "r"(a3), "r"(b0), "r"(b1));
}
__device__ __forceinline__ void mma3(float* d,
                                     u32 ah0, u32 ah1, u32 ah2, u32 ah3,
                                     u32 al0, u32 al1, u32 al2, u32 al3,
                                     u64 bx, u64 by) {
    u32 bh0 = (u32)bx, bh1 = (u32)by;
    u32 bl0 = (u32)(bx >> 32), bl1 = (u32)(by >> 32);
    mma_bf16(d[0], d[1], d[2], d[3], ah0, ah1, ah2, ah3, bh0, bh1);
    mma_bf16(d[0], d[1], d[2], d[3], al0, al1, al2, al3, bh0, bh1);
    mma_bf16(d[0], d[1], d[2], d[3], ah0, ah1, ah2, ah3, bl0, bl1);
}

// =====================================================================
__global__ void reset_kernel() {
    int i = blockIdx.x * blockDim.x + threadIdx.x;
    if (i < NTIME * NROWT) g_bar[i * BARPAD] = 0;
}

__global__ void prep_pack(const float* __restrict__ emb,
                          const float* __restrict__ W_in,
                          const float* __restrict__ W_out) {
    int i = blockIdx.x * blockDim.x + threadIdx.x;
    if (i < NALPH * 64) {
        int r = i >> 6, p = i & 63;
        g_emb_pk[i] = pack_hl(emb[r * NE + 2 * p], emb[r * NE + 2 * p + 1]);
    } else if (i < NALPH * 64 + NS * 64) {
        int j = i - NALPH * 64, n = j >> 6, p = j & 63;
        g_wf_pk[j] = pack_hl(W_in[n * FAN + 2 * p], W_in[n * FAN + 2 * p + 1]);
    } else if (i < NALPH * 64 + NS * 64 + NALPH * 256) {
        int j = i - NALPH * 64 - NS * 64, a = j >> 8, p = j & 255;
        g_wout_pk[j] = pack_hl(W_out[a * NS + 2 * p], W_out[a * NS + 2 * p + 1]);
    }
}

// =====================================================================
// Phase 1: fin via tensor cores.  64(bt) x 64(n) CTA tile, K=128.
// =====================================================================
__global__ void __launch_bounds__(256)
fin_kernel_mma(const int* __restrict__ w,
               const float* __restrict__ b_in) {
    extern __shared__ u64 smf[];
    u64* Aq = smf;             // [64][P2]
    u64* Bq = smf + 64 * P2;   // [64][P2]
    __shared__ int widx[64];

    const int tid  = threadIdx.x;
    const int lane = tid & 31, wrp = tid >> 5;
    const int g    = lane >> 2, tq = lane & 3;
    const int rg   = wrp & 3, ch = wrp >> 2;
    const int bt0  = blockIdx.x * 64;
    const int n0   = blockIdx.y * 64;

    if (tid < 64) {
        int rp = bt0 + tid;
        widx[tid] = w[((rp & 255) << 8) | (rp >> 8)];
    }
    __syncthreads();

    for (int s = tid; s < 64 * 64; s += 256) {
        int row = s >> 6, p = s & 63;
        Aq[row * P2 + PERM(p)] = g_emb_pk[widx[row] * 64 + p];
    }
    for (int s = tid; s < 64 * 64; s += 256) {
        int row = s >> 6, p = s & 63;
        Bq[row * P2 + PERM(p)] = g_wf_pk[(n0 + row) * 64 + p];
    }
    __syncthreads();

    const u64* ar0 = Aq + (rg * 16 + g) * P2;
    const u64* ar1 = ar0 + 8 * P2;
    const u64* br0 = Bq + (ch * 32 + g) * P2;
    const u64* br1 = br0 + 8 * P2;
    const u64* br2 = br0 + 16 * P2;
    const u64* br3 = br0 + 24 * P2;

    float d[4][4] = {};
    #pragma unroll
    for (int kk = 0; kk < 8; ++kk) {
        int off = 8 * kk + 2 * tq;
        ulonglong2 A0 = *(const ulonglong2*)(ar0 + off);
        ulonglong2 A1 = *(const ulonglong2*)(ar1 + off);
        u32 ah0=(u32)A0.x, ah1=(u32)A1.x, ah2=(u32)A0.y, ah3=(u32)A1.y;
        u32 al0=(u32)(A0.x>>32), al1=(u32)(A1.x>>32);
        u32 al2=(u32)(A0.y>>32), al3=(u32)(A1.y>>32);
        ulonglong2 B0 = *(const ulonglong2*)(br0 + off);
        ulonglong2 B1 = *(const ulonglong2*)(br1 + off);
        ulonglong2 B2 = *(const ulonglong2*)(br2 + off);
        ulonglong2 B3 = *(const ulonglong2*)(br3 + off);
        mma3(d[0], ah0,ah1,ah2,ah3, al0,al1,al2,al3, B0.x, B0.y);
        mma3(d[1], ah0,ah1,ah2,ah3, al0,al1,al2,al3, B1.x, B1.y);
        mma3(d[2], ah0,ah1,ah2,ah3, al0,al1,al2,al3, B2.x, B2.y);
        mma3(d[3], ah0,ah1,ah2,ah3, al0,al1,al2,al3, B3.x, B3.y);
    }

    int row0 = bt0 + rg * 16 + g, row1 = row0 + 8;
    #pragma unroll
    for (int j = 0; j < 4; ++j) {
        int col = n0 + ch * 32 + 8 * j + 2 * tq;
        float2 bi = *(const float2*)&b_in[col];
        *(float2*)&g_fin[row0 * NS + col] = make_float2(d[j][0] + bi.x, d[j][1] + bi.y);
        *(float2*)&g_fin[row1 * NS + col] = make_float2(d[j][2] + bi.x, d[j][3] + bi.y);
    }
}

// =====================================================================
// Phase 2: persistent recurrent kernel (R15 structure, PITCH=264).
// =====================================================================
__global__ void __launch_bounds__(256, 1)
rnn_kernel(const float* __restrict__ W_in) {
    extern __shared__ u64 smq[];
    u64*   Bq  = smq;                          // [64][PITCH]
    u64*   Aq  = smq + 64 * PITCH;             // [16][PITCH]
    float* Red = (float*)(smq + 80 * PITCH);   // [4][32][8]

    const int tid  = threadIdx.x;
    const int wrp  = tid >> 5;
    const int lane = tid & 31;
    const int g    = lane >> 2;
    const int tq   = lane & 3;
    const int cg   = wrp & 3;
    const int kh   = wrp >> 2;
    const int rowtile = blockIdx.x >> 3;
    const int coltile = blockIdx.x & 7;
    const int rb0 = rowtile * 16;
    const int cb0 = coltile * 64;

    for (int s = tid; s < 64 * 256; s += 256) {
        int n = s >> 8, p = s & 255;
        const float* wp = &W_in[(cb0 + n) * FAN + NE + 2 * p];
        Bq[n * PITCH + PERM(p)] = pack_hl(wp[0], wp[1]);
    }
    __syncthreads();

    const u64* arow0 = Aq + g * PITCH;
    const u64* arow1 = Aq + (g + 8) * PITCH;
    const u64* brow0 = Bq + (16 * cg + g) * PITCH;
    const u64* brow1 = Bq + (16 * cg + g + 8) * PITCH;

    const int r0 = rb0 + g, r1 = rb0 + g + 8;
    const int c0 = cb0 + 16 * cg + 2 * tq;
    const int c1 = c0 + 8;
    const int pg0 = c0 >> 1, pg1 = pg0 + 4;
    const int kbase = kh * 16;

    const int srow = tid >> 4;
    const int sp0  = tid & 15;

    float* redp = &Red[(cg * 32 + lane) * 8];

    float2 f00, f01, f10, f11;
    if (kh == 0) {
        f00 = *(const float2*)&g_fin[r0 * NS + c0];
        f01 = *(const float2*)&g_fin[r0 * NS + c1];
        f10 = *(const float2*)&g_fin[r1 * NS + c0];
        f11 = *(const float2*)&g_fin[r1 * NS + c1];
    }

    for (int t = 0; t < NTIME; ++t) {
        float d0=0.f,d1=0.f,d2=0.f,d3=0.f,d4=0.f,d5=0.f,d6=0.f,d7=0.f;

        if (t > 0) {
            const int* bar = &g_bar[((t - 1) * NROWT + rowtile) * BARPAD];
            while (ld_acq(bar) < NCOLT) { }

            const u64* src = &g_state_pk[(t - 1) & 1][(rb0 + srow) << 8];
            u64* dst = &Aq[srow * PITCH];
            #pragma unroll
            for (int j = 0; j < 16; ++j) {
                int idx = sp0 + 16 * j;
                dst[PERM(idx)] = __ldcg(&src[idx]);
            }
            __syncthreads();

            #pragma unroll
            for (int cc = 0; cc < 16; ++cc) {
                int off = 8 * (kbase + cc) + 2 * tq;
                ulonglong2 A0 = *(const ulonglong2*)(arow0 + off);
                ulonglong2 A1 = *(const ulonglong2*)(arow1 + off);
                ulonglong2 B0 = *(const ulonglong2*)(brow0 + off);
                ulonglong2 B1 = *(const ulonglong2*)(brow1 + off);
                u32 ah0 = (u32)A0.x, ah1 = (u32)A1.x, ah2 = (u32)A0.y, ah3 = (u32)A1.y;
                u32 al0 = (u32)(A0.x >> 32), al1 = (u32)(A1.x >> 32);
                u32 al2 = (u32)(A0.y >> 32), al3 = (u32)(A1.y >> 32);
                u32 bh0 = (u32)B0.x, bh1 = (u32)B0.y;
                u32 bl0 = (u32)(B0.x >> 32), bl1 = (u32)(B0.y >> 32);
                u32 ch0 = (u32)B1.x, ch1 = (u32)B1.y;
                u32 cl0 = (u32)(B1.x >> 32), cl1 = (u32)(B1.y >> 32);
                mma_bf16(d0,d1,d2,d3, ah0,ah1,ah2,ah3, bh0,bh1);
                mma_bf16(d0,d1,d2,d3, al0,al1,al2,al3, bh0,bh1);
                mma_bf16(d0,d1,d2,d3, ah0,ah1,ah2,ah3, bl0,bl1);
                mma_bf16(d4,d5,d6,d7, ah0,ah1,ah2,ah3, ch0,ch1);
                mma_bf16(d4,d5,d6,d7, al0,al1,al2,al3, ch0,ch1);
                mma_bf16(d4,d5,d6,d7, ah0,ah1,ah2,ah3, cl0,cl1);
            }

            if (kh == 1) {
                redp[0]=d0; redp[1]=d1; redp[2]=d2; redp[3]=d3;
                redp[4]=d4; redp[5]=d5; redp[6]=d6; redp[7]=d7;
            }
            __syncthreads();
            if (kh == 0) {
                d0 += redp[0]; d1 += redp[1]; d2 += redp[2]; d3 += redp[3];
                d4 += redp[4]; d5 += redp[5]; d6 += redp[6]; d7 += redp[7];
            }
        }

        if (kh == 0) {
            float v0 = tanh_fast(d0 + f00.x), v1 = tanh_fast(d1 + f00.y);
            float v2 = tanh_fast(d2 + f10.x), v3 = tanh_fast(d3 + f10.y);
            float v4 = tanh_fast(d4 + f01.x), v5 = tanh_fast(d5 + f01.y);
            float v6 = tanh_fast(d6 + f11.x), v7 = tanh_fast(d7 + f11.y);

            u64 pk00 = pack_hl(v0, v1), pk10 = pack_hl(v2, v3);
            u64 pk01 = pack_hl(v4, v5), pk11 = pack_hl(v6, v7);

            const int sel = t & 1;
            g_state_pk[sel][(r0 << 8) + pg0] = pk00;
            g_state_pk[sel][(r1 << 8) + pg0] = pk10;
            g_state_pk[sel][(r0 << 8) + pg1] = pk01;
            g_state_pk[sel][(r1 << 8) + pg1] = pk11;

            stcs_u64(&g_spk_log[(((unsigned)t * NBATCH + r0) << 8) + pg0], pk00);
            stcs_u64(&g_spk_log[(((unsigned)t * NBATCH + r1) << 8) + pg0], pk10);
            stcs_u64(&g_spk_log[(((unsigned)t * NBATCH + r0) << 8) + pg1], pk01);
            stcs_u64(&g_spk_log[(((unsigned)t * NBATCH + r1) << 8) + pg1], pk11);
        }
        __syncthreads();

        if (t + 1 < NTIME) {
            if (tid == 0)
                arrive_release(&g_bar[(t * NROWT + rowtile) * BARPAD]);
            if (kh == 0) {
                f00 = __ldcg((const float2*)&g_fin[((t + 1) * NBATCH + r0) * NS + c0]);
                f01 = __ldcg((const float2*)&g_fin[((t + 1) * NBATCH + r0) * NS + c1]);
                f10 = __ldcg((const float2*)&g_fin[((t + 1) * NBATCH + r1) * NS + c0]);
                f11 = __ldcg((const float2*)&g_fin[((t + 1) * NBATCH + r1) * NS + c1]);
            }
        }
    }
}

// =====================================================================
// Phase 3: y via tensor cores, K=512 in 4 chunks, SW-PIPELINED:
// chunk kc+1's A (DRAM-resident spk log) prefetched into registers
// while chunk kc's GEMM runs. Per thread: p = tid&63 fixed, rows
// r4+4i (i=0..15) -> 16-u64 register stage.
// =====================================================================
__global__ void __launch_bounds__(256)
out_kernel_mma(const float* __restrict__ b_out,
               float* __restrict__ y) {
    extern __shared__ u64 smo[];
    u64* Aq = smo;             // [64][P2]
    u64* Bq = smo + 64 * P2;   // [64][P2]
    __shared__ int rowmap[64];

    const int tid  = threadIdx.x;
    const int lane = tid & 31, wrp = tid >> 5;
    const int g    = lane >> 2, tq = lane & 3;
    const int rg   = wrp & 3, ch = wrp >> 2;
    const int bt0  = blockIdx.x * 64;
    const int a0   = blockIdx.y * 64;

    if (tid < 64) {
        int r = bt0 + tid;
        rowmap[tid] = ((r & 255) << 8) | (r >> 8);
    }
    __syncthreads();

    // staging geometry: p fixed, rows r4 + 4i
    const int p  = tid & 63;
    const int pp = PERM(p);
    const int r4 = tid >> 6;
    int lrow[16];
    #pragma unroll
    for (int i = 0; i < 16; ++i) lrow[i] = rowmap[r4 + 4 * i];

    const u64* ar0 = Aq + (rg * 16 + g) * P2;
    const u64* ar1 = ar0 + 8 * P2;
    const u64* br0 = Bq + (ch * 32 + g) * P2;
    const u64* br1 = br0 + 8 * P2;
    const u64* br2 = br0 + 16 * P2;
    const u64* br3 = br0 + 24 * P2;

    float d[4][4] = {};

    // preload chunk 0 A into registers
    u64 aR[16];
    #pragma unroll
    for (int i = 0; i < 16; ++i)
        aR[i] = __ldcg(&g_spk_log[lrow[i] * 256 + p]);

    for (int kc = 0; kc < 4; ++kc) {
        // STS A from regs; load+STS B (L2-hot wout_pk)
        #pragma unroll
        for (int i = 0; i < 16; ++i)
            Aq[(r4 + 4 * i) * P2 + pp] = aR[i];
        #pragma unroll
        for (int i = 0; i < 16; ++i)
            Bq[(r4 + 4 * i) * P2 + pp] =
                g_wout_pk[(a0 + r4 + 4 * i) * 256 + 64 * kc + p];
        __syncthreads();

        // prefetch next chunk's A (overlaps GEMM below)
        if (kc < 3) {
            #pragma unroll
            for (int i = 0; i < 16; ++i)
                aR[i] = __ldcg(&g_spk_log[lrow[i] * 256 + 64 * (kc + 1) + p]);
        }

        #pragma unroll
        for (int kk = 0; kk < 8; ++kk) {
            int off = 8 * kk + 2 * tq;
            ulonglong2 A0 = *(const ulonglong2*)(ar0 + off);
            ulonglong2 A1 = *(const ulonglong2*)(ar1 + off);
            u32 ah0=(u32)A0.x, ah1=(u32)A1.x, ah2=(u32)A0.y, ah3=(u32)A1.y;
            u32 al0=(u32)(A0.x>>32), al1=(u32)(A1.x>>32);
            u32 al2=(u32)(A0.y>>32), al3=(u32)(A1.y>>32);
            ulonglong2 B0 = *(const ulonglong2*)(br0 + off);
            ulonglong2 B1 = *(const ulonglong2*)(br1 + off);
            ulonglong2 B2 = *(const ulonglong2*)(br2 + off);
            ulonglong2 B3 = *(const ulonglong2*)(br3 + off);
            mma3(d[0], ah0,ah1,ah2,ah3, al0,al1,al2,al3, B0.x, B0.y);
            mma3(d[1], ah0,ah1,ah2,ah3, al0,al1,al2,al3, B1.x, B1.y);
            mma3(d[2], ah0,ah1,ah2,ah3, al0,al1,al2,al3, B2.x, B2.y);
            mma3(d[3], ah0,ah1,ah2,ah3, al0,al1,al2,al3, B3.x, B3.y);
        }
        __syncthreads();
    }

    int row0 = bt0 + rg * 16 + g, row1 = row0 + 8;
    #pragma unroll
    for (int j = 0; j < 4; ++j) {
        int col = a0 + ch * 32 + 8 * j + 2 * tq;
        float2 bo = *(const float2*)&b_out[col];
        *(float2*)&y[row0 * NALPH + col] = make_float2(d[j][0] + bo.x, d[j][1] + bo.y);
        *(float2*)&y[row1 * NALPH + col] = make_float2(d[j][2] + bo.x, d[j][3] + bo.y);
    }
}

// =====================================================================
// launch: reset, prep, fin, rnn, out   (rnn = 4th launch -> profiled)
// =====================================================================
extern "C" void kernel_launch(void* const* d_in, const int* in_sizes, int n_in,
                              void* d_out, int out_size) {
    const int*   w     = (const int*)  d_in[0];
    const float* emb   = (const float*)d_in[1];
    const float* W_in  = (const float*)d_in[2];
    const float* b_in  = (const float*)d_in[3];
    const float* W_out = (const float*)d_in[4];
    const float* b_out = (const float*)d_in[5];
    float* y = (float*)d_out;

    size_t rnn_smem = (size_t)80 * PITCH * sizeof(u64) + 4 * 32 * 8 * sizeof(float);
    size_t gem_smem = (size_t)128 * P2 * sizeof(u64);
    cudaFuncSetAttribute(rnn_kernel,
                         cudaFuncAttributeMaxDynamicSharedMemorySize, (int)rnn_smem);
    cudaFuncSetAttribute(fin_kernel_mma,
                         cudaFuncAttributeMaxDynamicSharedMemorySize, (int)gem_smem);
    cudaFuncSetAttribute(out_kernel_mma,
                         cudaFuncAttributeMaxDynamicSharedMemorySize, (int)gem_smem);

    reset_kernel<<<(NTIME * NROWT + 255) / 256, 256>>>();
    prep_pack<<<(NALPH * 64 + NS * 64 + NALPH * 256 + 255) / 256, 256>>>(emb, W_in, W_out);
    fin_kernel_mma<<<dim3(BT / 64, NS / 64), 256, gem_smem>>>(w, b_in);
    rnn_kernel<<<128, 256, rnn_smem>>>(W_in);
    out_kernel_mma<<<dim3(BT / 64, NALPH / 64), 256, gem_smem>>>(b_out, y);
}